// round 2
// baseline (speedup 1.0000x reference)
#include <cuda_runtime.h>
#include <math.h>

#define T_TOK 4096
#define DIMV 1024
#define HEADS 16
#define HD 64
#define S_LEN 2048
#define EXPERTS 8
#define HIDDEN 4096
#define CAP 1280
#define NASSIGN (2*T_TOK)

// ---------------- scratch (static __device__ globals; no allocs) ----------------
__device__ float g_h[(size_t)T_TOK*DIMV];
__device__ float g_qkv[(size_t)T_TOK*3*DIMV];
__device__ float g_q[(size_t)T_TOK*DIMV];
__device__ float g_k[(size_t)T_TOK*DIMV];
__device__ float g_v[(size_t)T_TOK*DIMV];
__device__ float g_attn[(size_t)T_TOK*DIMV];
__device__ float g_x2[(size_t)T_TOK*DIMV];
__device__ float g_h2[(size_t)T_TOK*DIMV];
__device__ float g_probs[(size_t)T_TOK*EXPERTS];
__device__ int   g_eid[NASSIGN];
__device__ float g_wass[NASSIGN];
__device__ int   g_pos[NASSIGN];
__device__ int   g_keep[NASSIGN];
__device__ int   g_cnt[EXPERTS];
__device__ float g_buf[(size_t)EXPERTS*CAP*DIMV];
__device__ float g_mid[(size_t)EXPERTS*CAP*HIDDEN];
__device__ float g_moe[(size_t)EXPERTS*CAP*DIMV];

// ---------------- small kernels ----------------

__global__ void zero_kernel(){
    size_t n = (size_t)EXPERTS*CAP*DIMV;
    for (size_t i = (size_t)blockIdx.x*blockDim.x + threadIdx.x; i < n;
         i += (size_t)gridDim.x*blockDim.x)
        g_buf[i] = 0.f;
}

__global__ void ln_kernel(const float* __restrict__ x, const float* __restrict__ g,
                          const float* __restrict__ b, float* __restrict__ out){
    int t = blockIdx.x;
    const float* xr = x + (size_t)t*DIMV;
    float s = 0.f, s2 = 0.f;
    for (int i = threadIdx.x; i < DIMV; i += 256){ float v = xr[i]; s += v; s2 += v*v; }
    __shared__ float rs[256], rs2[256];
    rs[threadIdx.x] = s; rs2[threadIdx.x] = s2;
    __syncthreads();
    for (int o = 128; o; o >>= 1){
        if (threadIdx.x < o){ rs[threadIdx.x] += rs[threadIdx.x+o]; rs2[threadIdx.x] += rs2[threadIdx.x+o]; }
        __syncthreads();
    }
    float mu  = rs[0]  * (1.f/DIMV);
    float var = rs2[0] * (1.f/DIMV) - mu*mu;
    float inv = rsqrtf(var + 1e-6f);
    float* orow = out + (size_t)t*DIMV;
    for (int i = threadIdx.x; i < DIMV; i += 256)
        orow[i] = (xr[i]-mu)*inv*g[i] + b[i];
}

__global__ void rope_split_kernel(const float* __restrict__ cosp, const float* __restrict__ sinp){
    int t = blockIdx.x;                 // token
    int b = t >> 11, s = t & 2047;
    const float* qkvr = g_qkv + (size_t)t*3*DIMV;
    for (int i = threadIdx.x; i < DIMV; i += 256){
        int h = i >> 6, d = i & 63;
        int bh = b*HEADS + h;
        size_t dst = ((size_t)bh*S_LEN + s)*HD + d;
        float c  = cosp[s*HD + d];
        float sn = sinp[s*HD + d];
        float q  = qkvr[i];
        float k  = qkvr[DIMV + i];
        float v  = qkvr[2*DIMV + i];
        float qr = (d < 32) ? -qkvr[i+32]        : qkvr[i-32];
        float kr = (d < 32) ? -qkvr[DIMV + i+32] : qkvr[DIMV + i-32];
        g_q[dst] = q*c + qr*sn;
        g_k[dst] = k*c + kr*sn;
        g_v[dst] = v;
    }
}

// ---------------- flash attention (64-query tile, online softmax) ----------------
__global__ void __launch_bounds__(256) attn_kernel(){
    int qt = blockIdx.x;   // 0..31
    int bh = blockIdx.y;   // 0..31
    int b = bh >> 4, h = bh & 15;
    int tid = threadIdx.x;
    int row = tid >> 2, tpr = tid & 3, d0 = tpr*16;
    __shared__ float Qs[64][65], Ks[64][65], Vs[64][65], Ps[64][65];
    const float* qb = g_q + ((size_t)bh*S_LEN + qt*64)*HD;
    const float* kb = g_k + (size_t)bh*S_LEN*HD;
    const float* vb = g_v + (size_t)bh*S_LEN*HD;
    for (int i = tid; i < 64*64; i += 256){
        int r = i >> 6, c = i & 63;
        Qs[r][c] = qb[r*64 + c] * 0.125f;   // 1/sqrt(64)
    }
    float m = -1e30f, l = 0.f, o[16];
    #pragma unroll
    for (int j = 0; j < 16; j++) o[j] = 0.f;

    for (int kt = 0; kt < 32; kt++){
        __syncthreads();   // protect Ks/Vs/Ps still being read by previous iter
        for (int i = tid; i < 64*64; i += 256){
            int r = i >> 6, c = i & 63;
            Ks[r][c] = kb[(kt*64 + r)*64 + c];
            Vs[r][c] = vb[(kt*64 + r)*64 + c];
        }
        __syncthreads();
        float s[16];
        #pragma unroll
        for (int j = 0; j < 16; j++) s[j] = 0.f;
        for (int k = 0; k < 64; k++){
            float qv = Qs[row][k];
            #pragma unroll
            for (int j = 0; j < 16; j++) s[j] += qv * Ks[d0+j][k];
        }
        float tmax = s[0];
        #pragma unroll
        for (int j = 1; j < 16; j++) tmax = fmaxf(tmax, s[j]);
        tmax = fmaxf(tmax, __shfl_xor_sync(0xffffffffu, tmax, 1));
        tmax = fmaxf(tmax, __shfl_xor_sync(0xffffffffu, tmax, 2));
        float mnew  = fmaxf(m, tmax);
        float scale = __expf(m - mnew);
        float tsum  = 0.f;
        #pragma unroll
        for (int j = 0; j < 16; j++){
            float p = __expf(s[j] - mnew);
            Ps[row][d0+j] = p;
            tsum += p;
        }
        tsum += __shfl_xor_sync(0xffffffffu, tsum, 1);
        tsum += __shfl_xor_sync(0xffffffffu, tsum, 2);
        l = l*scale + tsum;
        m = mnew;
        #pragma unroll
        for (int j = 0; j < 16; j++) o[j] *= scale;
        __syncthreads();   // Ps visible
        for (int key = 0; key < 64; key++){
            float p = Ps[row][key];
            #pragma unroll
            for (int j = 0; j < 16; j++) o[j] += p * Vs[key][d0+j];
        }
    }
    float inv = 1.f / l;
    int token = b*S_LEN + qt*64 + row;
    float* outp = g_attn + (size_t)token*DIMV + h*HD + d0;
    #pragma unroll
    for (int j = 0; j < 16; j++) outp[j] = o[j]*inv;
}

// ---------------- SGEMM: C = A[M,K] @ B[K,N] + bias, optional gelu / residual ----------------
__device__ __forceinline__ float gelu_f(float v){
    const float c = 0.7978845608028654f;
    return 0.5f*v*(1.f + tanhf(c*(v + 0.044715f*v*v*v)));
}

template<int EPI>  // 0: bias, 1: bias+gelu, 2: bias+residual
__global__ void __launch_bounds__(256) sgemm_kernel(
    const float* __restrict__ A, const float* __restrict__ B,
    const float* __restrict__ bias, const float* __restrict__ R,
    float* __restrict__ C, int M, int N, int K,
    long long sA, long long sB, long long sBias, long long sC)
{
    A    += (long long)blockIdx.z * sA;
    B    += (long long)blockIdx.z * sB;
    bias += (long long)blockIdx.z * sBias;
    C    += (long long)blockIdx.z * sC;
    int m0 = blockIdx.y*128, n0 = blockIdx.x*128;
    int tid = threadIdx.x;
    int tx = tid & 15, ty = tid >> 4;
    __shared__ float As[8][128];
    __shared__ float Bs[8][128];
    float acc[8][8];
    #pragma unroll
    for (int i = 0; i < 8; i++)
        #pragma unroll
        for (int j = 0; j < 8; j++) acc[i][j] = 0.f;

    int arow = tid >> 1, acol = (tid & 1)*4;
    int brow = tid >> 5, bcol = (tid & 31)*4;
    const float* Aptr = A + (size_t)(m0+arow)*K + acol;
    const float* Bptr = B + (size_t)brow*N + n0 + bcol;

    for (int k0 = 0; k0 < K; k0 += 8){
        float4 a4 = *(const float4*)Aptr;  Aptr += 8;
        float4 b4 = *(const float4*)Bptr;  Bptr += (size_t)8*N;
        As[acol+0][arow] = a4.x; As[acol+1][arow] = a4.y;
        As[acol+2][arow] = a4.z; As[acol+3][arow] = a4.w;
        *(float4*)&Bs[brow][bcol] = b4;
        __syncthreads();
        #pragma unroll
        for (int k = 0; k < 8; k++){
            float4 a0 = *(const float4*)&As[k][ty*4];
            float4 a1 = *(const float4*)&As[k][64 + ty*4];
            float4 b0 = *(const float4*)&Bs[k][tx*4];
            float4 b1 = *(const float4*)&Bs[k][64 + tx*4];
            float a[8] = {a0.x,a0.y,a0.z,a0.w,a1.x,a1.y,a1.z,a1.w};
            float b[8] = {b0.x,b0.y,b0.z,b0.w,b1.x,b1.y,b1.z,b1.w};
            #pragma unroll
            for (int i = 0; i < 8; i++)
                #pragma unroll
                for (int j = 0; j < 8; j++) acc[i][j] += a[i]*b[j];
        }
        __syncthreads();
    }
    #pragma unroll
    for (int gi = 0; gi < 2; gi++){
        int r = m0 + gi*64 + ty*4;
        #pragma unroll
        for (int gj = 0; gj < 2; gj++){
            int c = n0 + gj*64 + tx*4;
            #pragma unroll
            for (int i = 0; i < 4; i++){
                #pragma unroll
                for (int j = 0; j < 4; j++){
                    float v = acc[gi*4+i][gj*4+j] + bias[c+j];
                    if (EPI == 1) v = gelu_f(v);
                    if (EPI == 2) v += R[(size_t)(r+i)*N + c + j];
                    C[(size_t)(r+i)*N + c + j] = v;
                }
            }
        }
    }
}

// ---------------- MoE routing ----------------
__global__ void gate_kernel(const float* __restrict__ gate_w){
    int t = blockIdx.x;
    int warp = threadIdx.x >> 5, lane = threadIdx.x & 31;
    const float* hr = g_h2 + (size_t)t*DIMV;
    float part = 0.f;
    for (int d = lane; d < DIMV; d += 32) part += hr[d]*gate_w[d*EXPERTS + warp];
    for (int o = 16; o; o >>= 1) part += __shfl_xor_sync(0xffffffffu, part, o);
    __shared__ float lg[EXPERTS];
    if (lane == 0) lg[warp] = part;
    __syncthreads();
    if (threadIdx.x == 0){
        float mx = -1e30f;
        for (int e = 0; e < EXPERTS; e++) mx = fmaxf(mx, lg[e]);
        float ex[EXPERTS], sum = 0.f;
        for (int e = 0; e < EXPERTS; e++){ ex[e] = expf(lg[e]-mx); sum += ex[e]; }
        float inv = 1.f/sum;
        float p[EXPERTS];
        for (int e = 0; e < EXPERTS; e++){ p[e] = ex[e]*inv; g_probs[t*EXPERTS + e] = p[e]; }
        int i1 = 0; float v1 = p[0];
        for (int e = 1; e < EXPERTS; e++) if (p[e] > v1){ v1 = p[e]; i1 = e; }
        int i2 = -1; float v2 = -1.f;
        for (int e = 0; e < EXPERTS; e++) if (e != i1 && p[e] > v2){ v2 = p[e]; i2 = e; }
        float ws = v1 + v2;
        g_eid[t]          = i1;  g_eid[T_TOK + t]  = i2;
        g_wass[t]         = v1/ws; g_wass[T_TOK + t] = v2/ws;
    }
}

// rank within expert, in eid order j = k*T + t (matches topi.T.reshape(-1))
__global__ void pos_kernel(){
    int e = threadIdx.x;
    if (e < EXPERTS){
        int c = 0;
        for (int j = 0; j < NASSIGN; j++){
            if (g_eid[j] == e){
                g_pos[j]  = c;
                g_keep[j] = (c < CAP) ? 1 : 0;
                c++;
            }
        }
        g_cnt[e] = c;
    }
}

__global__ void scatter_kernel(){
    int j = blockIdx.x;
    if (!g_keep[j]) return;
    int tok = (j >= T_TOK) ? (j - T_TOK) : j;
    int e = g_eid[j], p = g_pos[j];
    const float* src = g_h2 + (size_t)tok*DIMV;
    float* dst = g_buf + ((size_t)e*CAP + p)*DIMV;
    for (int d = threadIdx.x; d < DIMV; d += 256) dst[d] = src[d];
}

__global__ void final_kernel(float* __restrict__ out){
    int t = blockIdx.x;
    int j0 = t, j1 = T_TOK + t;
    float w0 = g_keep[j0] ? g_wass[j0] : 0.f;
    float w1 = g_keep[j1] ? g_wass[j1] : 0.f;
    int p0 = min(g_pos[j0], CAP-1), p1 = min(g_pos[j1], CAP-1);
    size_t i0 = ((size_t)g_eid[j0]*CAP + p0)*DIMV;
    size_t i1 = ((size_t)g_eid[j1]*CAP + p1)*DIMV;
    const float* x2r = g_x2 + (size_t)t*DIMV;
    float* orow = out + (size_t)t*DIMV;
    for (int d = threadIdx.x; d < DIMV; d += 256)
        orow[d] = x2r[d] + w0*g_moe[i0 + d] + w1*g_moe[i1 + d];
}

__global__ void aux_kernel(float* __restrict__ out, int out_size){
    __shared__ float red[EXPERTS][257];
    float acc[EXPERTS];
    #pragma unroll
    for (int e = 0; e < EXPERTS; e++) acc[e] = 0.f;
    for (int t = threadIdx.x; t < T_TOK; t += 256){
        #pragma unroll
        for (int e = 0; e < EXPERTS; e++) acc[e] += g_probs[t*EXPERTS + e];
    }
    #pragma unroll
    for (int e = 0; e < EXPERTS; e++) red[e][threadIdx.x] = acc[e];
    __syncthreads();
    if (threadIdx.x == 0){
        float aux = 0.f;
        for (int e = 0; e < EXPERTS; e++){
            float s = 0.f;
            for (int i = 0; i < 256; i++) s += red[e][i];
            float me = s / (float)T_TOK;
            float ce = (float)g_cnt[e] / (float)(T_TOK*2);
            aux += me*ce;
        }
        if (out_size > T_TOK*DIMV) out[(size_t)T_TOK*DIMV] = (float)EXPERTS * aux;
    }
}

// ---------------- launch ----------------
extern "C" void kernel_launch(void* const* d_in, const int* in_sizes, int n_in,
                              void* d_out, int out_size){
    const float* x      = (const float*)d_in[0];
    const float* cosp   = (const float*)d_in[1];
    const float* sinp   = (const float*)d_in[2];
    const float* ln1g   = (const float*)d_in[3];
    const float* ln1b   = (const float*)d_in[4];
    const float* ln2g   = (const float*)d_in[5];
    const float* ln2b   = (const float*)d_in[6];
    const float* wqkv   = (const float*)d_in[7];
    const float* bqkv   = (const float*)d_in[8];
    const float* wo     = (const float*)d_in[9];
    const float* bo     = (const float*)d_in[10];
    const float* gate_w = (const float*)d_in[11];
    const float* w1     = (const float*)d_in[12];
    const float* b1     = (const float*)d_in[13];
    const float* w2     = (const float*)d_in[14];
    const float* b2     = (const float*)d_in[15];
    float* out = (float*)d_out;

    float *p_h, *p_qkv, *p_attn, *p_x2, *p_h2, *p_buf, *p_mid, *p_moe;
    cudaGetSymbolAddress((void**)&p_h,    g_h);
    cudaGetSymbolAddress((void**)&p_qkv,  g_qkv);
    cudaGetSymbolAddress((void**)&p_attn, g_attn);
    cudaGetSymbolAddress((void**)&p_x2,   g_x2);
    cudaGetSymbolAddress((void**)&p_h2,   g_h2);
    cudaGetSymbolAddress((void**)&p_buf,  g_buf);
    cudaGetSymbolAddress((void**)&p_mid,  g_mid);
    cudaGetSymbolAddress((void**)&p_moe,  g_moe);

    zero_kernel<<<512, 256>>>();
    ln_kernel<<<T_TOK, 256>>>(x, ln1g, ln1b, p_h);

    // qkv = h @ wqkv + bqkv   [4096,1024]x[1024,3072]
    sgemm_kernel<0><<<dim3(3072/128, T_TOK/128, 1), 256>>>(
        p_h, wqkv, bqkv, nullptr, p_qkv, T_TOK, 3072, DIMV, 0,0,0,0);

    rope_split_kernel<<<T_TOK, 256>>>(cosp, sinp);
    attn_kernel<<<dim3(S_LEN/64, 2*HEADS), 256>>>();

    // x2 = attn @ wo + bo + x
    sgemm_kernel<2><<<dim3(DIMV/128, T_TOK/128, 1), 256>>>(
        p_attn, wo, bo, x, p_x2, T_TOK, DIMV, DIMV, 0,0,0,0);

    ln_kernel<<<T_TOK, 256>>>(p_x2, ln2g, ln2b, p_h2);
    gate_kernel<<<T_TOK, 256>>>(gate_w);
    pos_kernel<<<1, 32>>>();
    scatter_kernel<<<NASSIGN, 256>>>();

    // mid = gelu(buf @ w1 + b1)   batched over experts
    sgemm_kernel<1><<<dim3(HIDDEN/128, CAP/128, EXPERTS), 256>>>(
        p_buf, w1, b1, nullptr, p_mid, CAP, HIDDEN, DIMV,
        (long long)CAP*DIMV, (long long)DIMV*HIDDEN, (long long)HIDDEN, (long long)CAP*HIDDEN);

    // moe = mid @ w2 + b2
    sgemm_kernel<0><<<dim3(DIMV/128, CAP/128, EXPERTS), 256>>>(
        p_mid, w2, b2, nullptr, p_moe, CAP, DIMV, HIDDEN,
        (long long)CAP*HIDDEN, (long long)HIDDEN*DIMV, (long long)DIMV, (long long)CAP*DIMV);

    final_kernel<<<T_TOK, 256>>>(out);
    aux_kernel<<<1, 256>>>(out, out_size);
}

// round 3
// speedup vs baseline: 2.3815x; 2.3815x over previous
#include <cuda_runtime.h>
#include <math.h>
#include <stdint.h>

#define T_TOK 4096
#define DIMV 1024
#define HEADS 16
#define HD 64
#define S_LEN 2048
#define EXPERTS 8
#define HIDDEN 4096
#define CAP 1280
#define NASSIGN (2*T_TOK)

// ---------------- scratch (static __device__ globals; no allocs) ----------------
__device__ float g_h[(size_t)T_TOK*DIMV];
__device__ float g_qkv[(size_t)T_TOK*3*DIMV];
__device__ float g_q[(size_t)T_TOK*DIMV];
__device__ float g_k[(size_t)T_TOK*DIMV];
__device__ float g_v[(size_t)T_TOK*DIMV];
__device__ float g_attn[(size_t)T_TOK*DIMV];
__device__ float g_x2[(size_t)T_TOK*DIMV];
__device__ float g_h2[(size_t)T_TOK*DIMV];
__device__ float g_probs[(size_t)T_TOK*EXPERTS];
__device__ int   g_eid[NASSIGN];
__device__ float g_wass[NASSIGN];
__device__ int   g_pos[NASSIGN];
__device__ int   g_keep[NASSIGN];
__device__ int   g_cnt[EXPERTS];
__device__ float g_buf[(size_t)EXPERTS*CAP*DIMV];
__device__ float g_mid[(size_t)EXPERTS*CAP*HIDDEN];
__device__ float g_moe[(size_t)EXPERTS*CAP*DIMV];

// ---------------- small kernels ----------------

__global__ void zero_kernel(){
    size_t n = (size_t)EXPERTS*CAP*DIMV;
    for (size_t i = (size_t)blockIdx.x*blockDim.x + threadIdx.x; i < n;
         i += (size_t)gridDim.x*blockDim.x)
        g_buf[i] = 0.f;
}

__global__ void ln_kernel(const float* __restrict__ x, const float* __restrict__ g,
                          const float* __restrict__ b, float* __restrict__ out){
    int t = blockIdx.x;
    const float* xr = x + (size_t)t*DIMV;
    float s = 0.f, s2 = 0.f;
    for (int i = threadIdx.x; i < DIMV; i += 256){ float v = xr[i]; s += v; s2 += v*v; }
    __shared__ float rs[256], rs2[256];
    rs[threadIdx.x] = s; rs2[threadIdx.x] = s2;
    __syncthreads();
    for (int o = 128; o; o >>= 1){
        if (threadIdx.x < o){ rs[threadIdx.x] += rs[threadIdx.x+o]; rs2[threadIdx.x] += rs2[threadIdx.x+o]; }
        __syncthreads();
    }
    float mu  = rs[0]  * (1.f/DIMV);
    float var = rs2[0] * (1.f/DIMV) - mu*mu;
    float inv = rsqrtf(var + 1e-6f);
    float* orow = out + (size_t)t*DIMV;
    for (int i = threadIdx.x; i < DIMV; i += 256)
        orow[i] = (xr[i]-mu)*inv*g[i] + b[i];
}

__global__ void rope_split_kernel(const float* __restrict__ cosp, const float* __restrict__ sinp){
    int t = blockIdx.x;                 // token
    int b = t >> 11, s = t & 2047;
    const float* qkvr = g_qkv + (size_t)t*3*DIMV;
    for (int i = threadIdx.x; i < DIMV; i += 256){
        int h = i >> 6, d = i & 63;
        int bh = b*HEADS + h;
        size_t dst = ((size_t)bh*S_LEN + s)*HD + d;
        float c  = cosp[s*HD + d];
        float sn = sinp[s*HD + d];
        float q  = qkvr[i];
        float k  = qkvr[DIMV + i];
        float v  = qkvr[2*DIMV + i];
        float qr = (d < 32) ? -qkvr[i+32]        : qkvr[i-32];
        float kr = (d < 32) ? -qkvr[DIMV + i+32] : qkvr[DIMV + i-32];
        g_q[dst] = q*c + qr*sn;
        g_k[dst] = k*c + kr*sn;
        g_v[dst] = v;
    }
}

// ---------------- flash attention (64-query tile, online softmax) ----------------
__global__ void __launch_bounds__(256) attn_kernel(){
    int qt = blockIdx.x;   // 0..31
    int bh = blockIdx.y;   // 0..31
    int b = bh >> 4, h = bh & 15;
    int tid = threadIdx.x;
    int row = tid >> 2, tpr = tid & 3, d0 = tpr*16;
    __shared__ float Qs[64][65], Ks[64][65], Vs[64][65], Ps[64][65];
    const float* qb = g_q + ((size_t)bh*S_LEN + qt*64)*HD;
    const float* kb = g_k + (size_t)bh*S_LEN*HD;
    const float* vb = g_v + (size_t)bh*S_LEN*HD;
    for (int i = tid; i < 64*64; i += 256){
        int r = i >> 6, c = i & 63;
        Qs[r][c] = qb[r*64 + c] * 0.125f;   // 1/sqrt(64)
    }
    float m = -1e30f, l = 0.f, o[16];
    #pragma unroll
    for (int j = 0; j < 16; j++) o[j] = 0.f;

    for (int kt = 0; kt < 32; kt++){
        __syncthreads();   // protect Ks/Vs/Ps still being read by previous iter
        for (int i = tid; i < 64*64; i += 256){
            int r = i >> 6, c = i & 63;
            Ks[r][c] = kb[(kt*64 + r)*64 + c];
            Vs[r][c] = vb[(kt*64 + r)*64 + c];
        }
        __syncthreads();
        float s[16];
        #pragma unroll
        for (int j = 0; j < 16; j++) s[j] = 0.f;
        for (int k = 0; k < 64; k++){
            float qv = Qs[row][k];
            #pragma unroll
            for (int j = 0; j < 16; j++) s[j] += qv * Ks[d0+j][k];
        }
        float tmax = s[0];
        #pragma unroll
        for (int j = 1; j < 16; j++) tmax = fmaxf(tmax, s[j]);
        tmax = fmaxf(tmax, __shfl_xor_sync(0xffffffffu, tmax, 1));
        tmax = fmaxf(tmax, __shfl_xor_sync(0xffffffffu, tmax, 2));
        float mnew  = fmaxf(m, tmax);
        float scale = __expf(m - mnew);
        float tsum  = 0.f;
        #pragma unroll
        for (int j = 0; j < 16; j++){
            float p = __expf(s[j] - mnew);
            Ps[row][d0+j] = p;
            tsum += p;
        }
        tsum += __shfl_xor_sync(0xffffffffu, tsum, 1);
        tsum += __shfl_xor_sync(0xffffffffu, tsum, 2);
        l = l*scale + tsum;
        m = mnew;
        #pragma unroll
        for (int j = 0; j < 16; j++) o[j] *= scale;
        __syncthreads();   // Ps visible
        for (int key = 0; key < 64; key++){
            float p = Ps[row][key];
            #pragma unroll
            for (int j = 0; j < 16; j++) o[j] += p * Vs[key][d0+j];
        }
    }
    float inv = 1.f / l;
    int token = b*S_LEN + qt*64 + row;
    float* outp = g_attn + (size_t)token*DIMV + h*HD + d0;
    #pragma unroll
    for (int j = 0; j < 16; j++) outp[j] = o[j]*inv;
}

// ---------------- TF32 tensor-core GEMM ----------------
// C[M,N] = A[M,K] @ B[K,N] + bias, optional gelu / residual epilogue.
// Block tile 128x128, K-tile 32, 8 warps (2x4), warp tile 64x32 (4x4 m16n8k8).

__device__ __forceinline__ float gelu_f(float v){
    const float c = 0.7978845608028654f;
    return 0.5f*v*(1.f + tanhf(c*(v + 0.044715f*v*v*v)));
}

__device__ __forceinline__ uint32_t to_tf32(float x){
    uint32_t r;
    asm("cvt.rna.tf32.f32 %0, %1;" : "=r"(r) : "f"(x));
    return r;
}

__device__ __forceinline__ void mma_tf32(float* c, const uint32_t* a, const uint32_t* b){
    asm volatile(
        "mma.sync.aligned.m16n8k8.row.col.f32.tf32.tf32.f32 "
        "{%0,%1,%2,%3}, {%4,%5,%6,%7}, {%8,%9}, {%0,%1,%2,%3};"
        : "+f"(c[0]), "+f"(c[1]), "+f"(c[2]), "+f"(c[3])
        : "r"(a[0]), "r"(a[1]), "r"(a[2]), "r"(a[3]), "r"(b[0]), "r"(b[1]));
}

template<int EPI>  // 0: bias, 1: bias+gelu, 2: bias+residual
__global__ void __launch_bounds__(256) tgemm_kernel(
    const float* __restrict__ A, const float* __restrict__ B,
    const float* __restrict__ bias, const float* __restrict__ R,
    float* __restrict__ C, int M, int N, int K,
    long long sA, long long sB, long long sBias, long long sC)
{
    A    += (long long)blockIdx.z * sA;
    B    += (long long)blockIdx.z * sB;
    bias += (long long)blockIdx.z * sBias;
    C    += (long long)blockIdx.z * sC;
    const int m0 = blockIdx.y*128, n0 = blockIdx.x*128;
    const int tid  = threadIdx.x;
    const int warp = tid >> 5, lane = tid & 31;
    const int wM = warp & 1;        // 0..1 -> 64 rows each
    const int wN = warp >> 1;       // 0..3 -> 32 cols each
    const int g  = lane >> 2;       // groupID 0..7
    const int tg = lane & 3;        // threadID_in_group 0..3

    // conflict-free fragment layouts:
    // As stride 36 (=4 mod 32) -> bank = 4*g + tg (distinct)
    // Bs stride 136 (=8 mod 32) -> bank = 8*tg + g (distinct)
    __shared__ float As[128][36];
    __shared__ float Bs[32][136];

    float acc[4][4][4];
    #pragma unroll
    for (int mi = 0; mi < 4; mi++)
        #pragma unroll
        for (int ni = 0; ni < 4; ni++)
            #pragma unroll
            for (int q = 0; q < 4; q++) acc[mi][ni][q] = 0.f;

    // global prefetch: A tile 128x32, B tile 32x128 (float4 per thread, x4 each)
    const int aRow = tid >> 3, aCol = (tid & 7)*4;   // rows aRow + 32*i
    const int bRow = tid >> 5, bCol = (tid & 31)*4;  // rows bRow + 8*i
    const float* Ag = A + (size_t)(m0 + aRow)*K + aCol;
    const float* Bg = B + (size_t)bRow*N + n0 + bCol;

    float4 pa[4], pb[4];
    #pragma unroll
    for (int i = 0; i < 4; i++) pa[i] = *(const float4*)(Ag + (size_t)(32*i)*K);
    #pragma unroll
    for (int i = 0; i < 4; i++) pb[i] = *(const float4*)(Bg + (size_t)(8*i)*N);

    const int nkt = K >> 5;
    for (int kt = 0; kt < nkt; kt++){
        // store prefetched tile to smem, converting to tf32 bits
        #pragma unroll
        for (int i = 0; i < 4; i++){
            uint4 w;
            w.x = to_tf32(pa[i].x); w.y = to_tf32(pa[i].y);
            w.z = to_tf32(pa[i].z); w.w = to_tf32(pa[i].w);
            *(uint4*)&As[aRow + 32*i][aCol] = w;
        }
        #pragma unroll
        for (int i = 0; i < 4; i++){
            uint4 w;
            w.x = to_tf32(pb[i].x); w.y = to_tf32(pb[i].y);
            w.z = to_tf32(pb[i].z); w.w = to_tf32(pb[i].w);
            *(uint4*)&Bs[bRow + 8*i][bCol] = w;
        }
        __syncthreads();

        if (kt + 1 < nkt){
            Ag += 32; Bg += (size_t)32*N;
            #pragma unroll
            for (int i = 0; i < 4; i++) pa[i] = *(const float4*)(Ag + (size_t)(32*i)*K);
            #pragma unroll
            for (int i = 0; i < 4; i++) pb[i] = *(const float4*)(Bg + (size_t)(8*i)*N);
        }

        #pragma unroll
        for (int k8 = 0; k8 < 32; k8 += 8){
            uint32_t af[4][4], bf[4][2];
            #pragma unroll
            for (int mi = 0; mi < 4; mi++){
                int r = wM*64 + mi*16 + g;
                af[mi][0] = __float_as_uint(As[r    ][k8 + tg    ]);
                af[mi][1] = __float_as_uint(As[r + 8][k8 + tg    ]);
                af[mi][2] = __float_as_uint(As[r    ][k8 + tg + 4]);
                af[mi][3] = __float_as_uint(As[r + 8][k8 + tg + 4]);
            }
            #pragma unroll
            for (int ni = 0; ni < 4; ni++){
                int c = wN*32 + ni*8 + g;
                bf[ni][0] = __float_as_uint(Bs[k8 + tg    ][c]);
                bf[ni][1] = __float_as_uint(Bs[k8 + tg + 4][c]);
            }
            #pragma unroll
            for (int mi = 0; mi < 4; mi++)
                #pragma unroll
                for (int ni = 0; ni < 4; ni++)
                    mma_tf32(acc[mi][ni], af[mi], bf[ni]);
        }
        __syncthreads();
    }

    // epilogue: c0,c1 at (g, tg*2 / tg*2+1); c2,c3 at (g+8, ...)
    #pragma unroll
    for (int mi = 0; mi < 4; mi++){
        int r0 = m0 + wM*64 + mi*16 + g;
        #pragma unroll
        for (int ni = 0; ni < 4; ni++){
            int c0 = n0 + wN*32 + ni*8 + tg*2;
            float bv0 = bias[c0], bv1 = bias[c0+1];
            float v00 = acc[mi][ni][0] + bv0;
            float v01 = acc[mi][ni][1] + bv1;
            float v10 = acc[mi][ni][2] + bv0;
            float v11 = acc[mi][ni][3] + bv1;
            if (EPI == 1){
                v00 = gelu_f(v00); v01 = gelu_f(v01);
                v10 = gelu_f(v10); v11 = gelu_f(v11);
            }
            if (EPI == 2){
                v00 += R[(size_t)r0*N + c0];     v01 += R[(size_t)r0*N + c0 + 1];
                v10 += R[(size_t)(r0+8)*N + c0]; v11 += R[(size_t)(r0+8)*N + c0 + 1];
            }
            *(float2*)&C[(size_t)r0*N + c0]     = make_float2(v00, v01);
            *(float2*)&C[(size_t)(r0+8)*N + c0] = make_float2(v10, v11);
        }
    }
}

// ---------------- MoE routing ----------------
__global__ void gate_kernel(const float* __restrict__ gate_w){
    int t = blockIdx.x;
    int warp = threadIdx.x >> 5, lane = threadIdx.x & 31;
    const float* hr = g_h2 + (size_t)t*DIMV;
    float part = 0.f;
    for (int d = lane; d < DIMV; d += 32) part += hr[d]*gate_w[d*EXPERTS + warp];
    for (int o = 16; o; o >>= 1) part += __shfl_xor_sync(0xffffffffu, part, o);
    __shared__ float lg[EXPERTS];
    if (lane == 0) lg[warp] = part;
    __syncthreads();
    if (threadIdx.x == 0){
        float mx = -1e30f;
        for (int e = 0; e < EXPERTS; e++) mx = fmaxf(mx, lg[e]);
        float ex[EXPERTS], sum = 0.f;
        for (int e = 0; e < EXPERTS; e++){ ex[e] = expf(lg[e]-mx); sum += ex[e]; }
        float inv = 1.f/sum;
        float p[EXPERTS];
        for (int e = 0; e < EXPERTS; e++){ p[e] = ex[e]*inv; g_probs[t*EXPERTS + e] = p[e]; }
        int i1 = 0; float v1 = p[0];
        for (int e = 1; e < EXPERTS; e++) if (p[e] > v1){ v1 = p[e]; i1 = e; }
        int i2 = -1; float v2 = -1.f;
        for (int e = 0; e < EXPERTS; e++) if (e != i1 && p[e] > v2){ v2 = p[e]; i2 = e; }
        float ws = v1 + v2;
        g_eid[t]          = i1;  g_eid[T_TOK + t]  = i2;
        g_wass[t]         = v1/ws; g_wass[T_TOK + t] = v2/ws;
    }
}

// rank within expert, in eid order j = k*T + t (matches topi.T.reshape(-1))
__global__ void pos_kernel(){
    int e = threadIdx.x;
    if (e < EXPERTS){
        int c = 0;
        for (int j = 0; j < NASSIGN; j++){
            if (g_eid[j] == e){
                g_pos[j]  = c;
                g_keep[j] = (c < CAP) ? 1 : 0;
                c++;
            }
        }
        g_cnt[e] = c;
    }
}

__global__ void scatter_kernel(){
    int j = blockIdx.x;
    if (!g_keep[j]) return;
    int tok = (j >= T_TOK) ? (j - T_TOK) : j;
    int e = g_eid[j], p = g_pos[j];
    const float* src = g_h2 + (size_t)tok*DIMV;
    float* dst = g_buf + ((size_t)e*CAP + p)*DIMV;
    for (int d = threadIdx.x; d < DIMV; d += 256) dst[d] = src[d];
}

__global__ void final_kernel(float* __restrict__ out){
    int t = blockIdx.x;
    int j0 = t, j1 = T_TOK + t;
    float w0 = g_keep[j0] ? g_wass[j0] : 0.f;
    float w1 = g_keep[j1] ? g_wass[j1] : 0.f;
    int p0 = min(g_pos[j0], CAP-1), p1 = min(g_pos[j1], CAP-1);
    size_t i0 = ((size_t)g_eid[j0]*CAP + p0)*DIMV;
    size_t i1 = ((size_t)g_eid[j1]*CAP + p1)*DIMV;
    const float* x2r = g_x2 + (size_t)t*DIMV;
    float* orow = out + (size_t)t*DIMV;
    for (int d = threadIdx.x; d < DIMV; d += 256)
        orow[d] = x2r[d] + w0*g_moe[i0 + d] + w1*g_moe[i1 + d];
}

__global__ void aux_kernel(float* __restrict__ out, int out_size){
    __shared__ float red[EXPERTS][257];
    float acc[EXPERTS];
    #pragma unroll
    for (int e = 0; e < EXPERTS; e++) acc[e] = 0.f;
    for (int t = threadIdx.x; t < T_TOK; t += 256){
        #pragma unroll
        for (int e = 0; e < EXPERTS; e++) acc[e] += g_probs[t*EXPERTS + e];
    }
    #pragma unroll
    for (int e = 0; e < EXPERTS; e++) red[e][threadIdx.x] = acc[e];
    __syncthreads();
    if (threadIdx.x == 0){
        float aux = 0.f;
        for (int e = 0; e < EXPERTS; e++){
            float s = 0.f;
            for (int i = 0; i < 256; i++) s += red[e][i];
            float me = s / (float)T_TOK;
            float ce = (float)g_cnt[e] / (float)(T_TOK*2);
            aux += me*ce;
        }
        if (out_size > T_TOK*DIMV) out[(size_t)T_TOK*DIMV] = (float)EXPERTS * aux;
    }
}

// ---------------- launch ----------------
extern "C" void kernel_launch(void* const* d_in, const int* in_sizes, int n_in,
                              void* d_out, int out_size){
    const float* x      = (const float*)d_in[0];
    const float* cosp   = (const float*)d_in[1];
    const float* sinp   = (const float*)d_in[2];
    const float* ln1g   = (const float*)d_in[3];
    const float* ln1b   = (const float*)d_in[4];
    const float* ln2g   = (const float*)d_in[5];
    const float* ln2b   = (const float*)d_in[6];
    const float* wqkv   = (const float*)d_in[7];
    const float* bqkv   = (const float*)d_in[8];
    const float* wo     = (const float*)d_in[9];
    const float* bo     = (const float*)d_in[10];
    const float* gate_w = (const float*)d_in[11];
    const float* w1     = (const float*)d_in[12];
    const float* b1     = (const float*)d_in[13];
    const float* w2     = (const float*)d_in[14];
    const float* b2     = (const float*)d_in[15];
    float* out = (float*)d_out;

    float *p_h, *p_qkv, *p_attn, *p_x2, *p_h2, *p_buf, *p_mid, *p_moe;
    cudaGetSymbolAddress((void**)&p_h,    g_h);
    cudaGetSymbolAddress((void**)&p_qkv,  g_qkv);
    cudaGetSymbolAddress((void**)&p_attn, g_attn);
    cudaGetSymbolAddress((void**)&p_x2,   g_x2);
    cudaGetSymbolAddress((void**)&p_h2,   g_h2);
    cudaGetSymbolAddress((void**)&p_buf,  g_buf);
    cudaGetSymbolAddress((void**)&p_mid,  g_mid);
    cudaGetSymbolAddress((void**)&p_moe,  g_moe);

    zero_kernel<<<512, 256>>>();
    ln_kernel<<<T_TOK, 256>>>(x, ln1g, ln1b, p_h);

    // qkv = h @ wqkv + bqkv   [4096,1024]x[1024,3072]
    tgemm_kernel<0><<<dim3(3072/128, T_TOK/128, 1), 256>>>(
        p_h, wqkv, bqkv, nullptr, p_qkv, T_TOK, 3072, DIMV, 0,0,0,0);

    rope_split_kernel<<<T_TOK, 256>>>(cosp, sinp);
    attn_kernel<<<dim3(S_LEN/64, 2*HEADS), 256>>>();

    // x2 = attn @ wo + bo + x
    tgemm_kernel<2><<<dim3(DIMV/128, T_TOK/128, 1), 256>>>(
        p_attn, wo, bo, x, p_x2, T_TOK, DIMV, DIMV, 0,0,0,0);

    ln_kernel<<<T_TOK, 256>>>(p_x2, ln2g, ln2b, p_h2);
    gate_kernel<<<T_TOK, 256>>>(gate_w);
    pos_kernel<<<1, 32>>>();
    scatter_kernel<<<NASSIGN, 256>>>();

    // mid = gelu(buf @ w1 + b1)   batched over experts
    tgemm_kernel<1><<<dim3(HIDDEN/128, CAP/128, EXPERTS), 256>>>(
        p_buf, w1, b1, nullptr, p_mid, CAP, HIDDEN, DIMV,
        (long long)CAP*DIMV, (long long)DIMV*HIDDEN, (long long)HIDDEN, (long long)CAP*HIDDEN);

    // moe = mid @ w2 + b2
    tgemm_kernel<0><<<dim3(DIMV/128, CAP/128, EXPERTS), 256>>>(
        p_mid, w2, b2, nullptr, p_moe, CAP, DIMV, HIDDEN,
        (long long)CAP*HIDDEN, (long long)HIDDEN*DIMV, (long long)DIMV, (long long)CAP*DIMV);

    final_kernel<<<T_TOK, 256>>>(out);
    aux_kernel<<<1, 256>>>(out, out_size);
}

// round 5
// speedup vs baseline: 8.3841x; 3.5206x over previous
#include <cuda_runtime.h>
#include <math.h>
#include <stdint.h>

#define T_TOK 4096
#define DIMV 1024
#define HEADS 16
#define HD 64
#define S_LEN 2048
#define EXPERTS 8
#define HIDDEN 4096
#define CAP 1280
#define NASSIGN (2*T_TOK)

// ---------------- scratch (static __device__ globals; no allocs) ----------------
__device__ float g_h[(size_t)T_TOK*DIMV];
__device__ float g_qkv[(size_t)T_TOK*3*DIMV];
__device__ float g_q[(size_t)T_TOK*DIMV];
__device__ float g_k[(size_t)T_TOK*DIMV];
__device__ float g_v[(size_t)T_TOK*DIMV];
__device__ float g_attn[(size_t)T_TOK*DIMV];
__device__ float g_x2[(size_t)T_TOK*DIMV];
__device__ float g_h2[(size_t)T_TOK*DIMV];
__device__ float g_probs[(size_t)T_TOK*EXPERTS];
__device__ int   g_eid[NASSIGN];
__device__ float g_wass[NASSIGN];
__device__ int   g_pos[NASSIGN];
__device__ int   g_keep[NASSIGN];
__device__ int   g_cnt[EXPERTS];
__device__ float g_buf[(size_t)EXPERTS*CAP*DIMV];
__device__ float g_mid[(size_t)EXPERTS*CAP*HIDDEN];
__device__ float g_moe[(size_t)EXPERTS*CAP*DIMV];

// ---------------- helpers ----------------
__device__ __forceinline__ void mma_tf32(float* c, const uint32_t* a, const uint32_t* b){
    asm volatile(
        "mma.sync.aligned.m16n8k8.row.col.f32.tf32.tf32.f32 "
        "{%0,%1,%2,%3}, {%4,%5,%6,%7}, {%8,%9}, {%0,%1,%2,%3};"
        : "+f"(c[0]), "+f"(c[1]), "+f"(c[2]), "+f"(c[3])
        : "r"(a[0]), "r"(a[1]), "r"(a[2]), "r"(a[3]), "r"(b[0]), "r"(b[1]));
}

__device__ __forceinline__ void cp_async16(void* smem_dst, const void* gmem_src){
    uint32_t s = (uint32_t)__cvta_generic_to_shared(smem_dst);
    asm volatile("cp.async.cg.shared.global [%0], [%1], 16;\n" :: "r"(s), "l"(gmem_src));
}
__device__ __forceinline__ void cp_commit(){ asm volatile("cp.async.commit_group;\n"); }
template<int N> __device__ __forceinline__ void cp_wait(){ asm volatile("cp.async.wait_group %0;\n" :: "n"(N)); }

__device__ __forceinline__ float gelu_f(float v){
    const float c = 0.7978845608028654f;
    return 0.5f*v*(1.f + tanhf(c*(v + 0.044715f*v*v*v)));
}

// ---------------- small kernels ----------------
__global__ void zero_kernel(){
    size_t n = (size_t)EXPERTS*CAP*DIMV;
    for (size_t i = (size_t)blockIdx.x*blockDim.x + threadIdx.x; i < n;
         i += (size_t)gridDim.x*blockDim.x)
        g_buf[i] = 0.f;
}

__global__ void ln_kernel(const float* __restrict__ x, const float* __restrict__ g,
                          const float* __restrict__ b, float* __restrict__ out){
    int t = blockIdx.x;
    const float* xr = x + (size_t)t*DIMV;
    float s = 0.f, s2 = 0.f;
    for (int i = threadIdx.x; i < DIMV; i += 256){ float v = xr[i]; s += v; s2 += v*v; }
    __shared__ float rs[256], rs2[256];
    rs[threadIdx.x] = s; rs2[threadIdx.x] = s2;
    __syncthreads();
    for (int o = 128; o; o >>= 1){
        if (threadIdx.x < o){ rs[threadIdx.x] += rs[threadIdx.x+o]; rs2[threadIdx.x] += rs2[threadIdx.x+o]; }
        __syncthreads();
    }
    float mu  = rs[0]  * (1.f/DIMV);
    float var = rs2[0] * (1.f/DIMV) - mu*mu;
    float inv = rsqrtf(var + 1e-6f);
    float* orow = out + (size_t)t*DIMV;
    for (int i = threadIdx.x; i < DIMV; i += 256)
        orow[i] = (xr[i]-mu)*inv*g[i] + b[i];
}

__global__ void rope_split_kernel(const float* __restrict__ cosp, const float* __restrict__ sinp){
    int t = blockIdx.x;
    int b = t >> 11, s = t & 2047;
    const float* qkvr = g_qkv + (size_t)t*3*DIMV;
    for (int i = threadIdx.x; i < DIMV; i += 256){
        int h = i >> 6, d = i & 63;
        int bh = b*HEADS + h;
        size_t dst = ((size_t)bh*S_LEN + s)*HD + d;
        float c  = cosp[s*HD + d];
        float sn = sinp[s*HD + d];
        float q  = qkvr[i];
        float k  = qkvr[DIMV + i];
        float v  = qkvr[2*DIMV + i];
        float qr = (d < 32) ? -qkvr[i+32]        : qkvr[i-32];
        float kr = (d < 32) ? -qkvr[DIMV + i+32] : qkvr[DIMV + i-32];
        g_q[dst] = q*c + qr*sn;
        g_k[dst] = k*c + kr*sn;
        g_v[dst] = v;
    }
}

// ---------------- tensor-core flash attention ----------------
// CTA: 128 threads (4 warps), 64 queries x one (b,h). Warp w owns rows [16w,16w+16).
#define APAD 68
__global__ void __launch_bounds__(128) attn_tc_kernel(){
    extern __shared__ float sm[];
    float* QP = sm;
    float* Ks = sm + 64*APAD;
    float* Vs = sm + 2*64*APAD;
    int qt = blockIdx.x, bh = blockIdx.y;
    int b = bh >> 4, h = bh & 15;
    int tid = threadIdx.x, warp = tid >> 5, lane = tid & 31;
    int g = lane >> 2, tg = lane & 3;
    int q0 = warp*16;

    const float* qb = g_q + ((size_t)bh*S_LEN + (size_t)qt*64)*HD;
    const float* kb = g_k + (size_t)bh*S_LEN*HD;
    const float* vb = g_v + (size_t)bh*S_LEN*HD;

    // stage Q (pre-scaled)
    for (int f = tid; f < 64*16; f += 128){
        int r = f >> 4, c4 = (f & 15)*4;
        float4 v = *(const float4*)(qb + r*HD + c4);
        v.x *= 0.125f; v.y *= 0.125f; v.z *= 0.125f; v.w *= 0.125f;
        *(float4*)&QP[r*APAD + c4] = v;
    }
    __syncthreads();
    uint32_t qf[8][4];
    #pragma unroll
    for (int k8 = 0; k8 < 8; k8++){
        qf[k8][0] = __float_as_uint(QP[(q0+g  )*APAD + k8*8 + tg    ]);
        qf[k8][1] = __float_as_uint(QP[(q0+g+8)*APAD + k8*8 + tg    ]);
        qf[k8][2] = __float_as_uint(QP[(q0+g  )*APAD + k8*8 + tg + 4]);
        qf[k8][3] = __float_as_uint(QP[(q0+g+8)*APAD + k8*8 + tg + 4]);
    }
    __syncthreads();   // QP becomes P region

    float m0 = -1e30f, m1 = -1e30f, l0 = 0.f, l1 = 0.f;
    float o[8][4];
    #pragma unroll
    for (int n8 = 0; n8 < 8; n8++){ o[n8][0]=0.f; o[n8][1]=0.f; o[n8][2]=0.f; o[n8][3]=0.f; }

    for (int kt = 0; kt < S_LEN/64; kt++){
        __syncthreads();
        for (int f = tid; f < 64*16; f += 128){
            int r = f >> 4, c4 = (f & 15)*4;
            *(float4*)&Ks[r*APAD + c4] = *(const float4*)(kb + (size_t)(kt*64 + r)*HD + c4);
            *(float4*)&Vs[r*APAD + c4] = *(const float4*)(vb + (size_t)(kt*64 + r)*HD + c4);
        }
        __syncthreads();

        // scores: S = Q @ K^T   (16x64 per warp)
        float sc[8][4];
        #pragma unroll
        for (int n8 = 0; n8 < 8; n8++){
            sc[n8][0]=0.f; sc[n8][1]=0.f; sc[n8][2]=0.f; sc[n8][3]=0.f;
            #pragma unroll
            for (int k8 = 0; k8 < 8; k8++){
                uint32_t bf[2];
                bf[0] = __float_as_uint(Ks[(n8*8+g)*APAD + k8*8 + tg    ]);
                bf[1] = __float_as_uint(Ks[(n8*8+g)*APAD + k8*8 + tg + 4]);
                mma_tf32(sc[n8], qf[k8], bf);
            }
        }
        // online softmax (rows g, g+8)
        float mt0 = -1e30f, mt1 = -1e30f;
        #pragma unroll
        for (int n8 = 0; n8 < 8; n8++){
            mt0 = fmaxf(mt0, fmaxf(sc[n8][0], sc[n8][1]));
            mt1 = fmaxf(mt1, fmaxf(sc[n8][2], sc[n8][3]));
        }
        mt0 = fmaxf(mt0, __shfl_xor_sync(0xffffffffu, mt0, 1));
        mt0 = fmaxf(mt0, __shfl_xor_sync(0xffffffffu, mt0, 2));
        mt1 = fmaxf(mt1, __shfl_xor_sync(0xffffffffu, mt1, 1));
        mt1 = fmaxf(mt1, __shfl_xor_sync(0xffffffffu, mt1, 2));
        float mn0 = fmaxf(m0, mt0), mn1 = fmaxf(m1, mt1);
        float sc0 = __expf(m0 - mn0), sc1 = __expf(m1 - mn1);
        float s0 = 0.f, s1 = 0.f;
        #pragma unroll
        for (int n8 = 0; n8 < 8; n8++){
            float p0 = __expf(sc[n8][0] - mn0);
            float p1 = __expf(sc[n8][1] - mn0);
            float p2 = __expf(sc[n8][2] - mn1);
            float p3 = __expf(sc[n8][3] - mn1);
            s0 += p0 + p1;  s1 += p2 + p3;
            *(float2*)&QP[(q0+g  )*APAD + n8*8 + 2*tg] = make_float2(p0, p1);
            *(float2*)&QP[(q0+g+8)*APAD + n8*8 + 2*tg] = make_float2(p2, p3);
        }
        s0 += __shfl_xor_sync(0xffffffffu, s0, 1);
        s0 += __shfl_xor_sync(0xffffffffu, s0, 2);
        s1 += __shfl_xor_sync(0xffffffffu, s1, 1);
        s1 += __shfl_xor_sync(0xffffffffu, s1, 2);
        l0 = l0*sc0 + s0;  l1 = l1*sc1 + s1;
        m0 = mn0;  m1 = mn1;
        #pragma unroll
        for (int n8 = 0; n8 < 8; n8++){
            o[n8][0] *= sc0; o[n8][1] *= sc0; o[n8][2] *= sc1; o[n8][3] *= sc1;
        }
        __syncwarp();   // P (warp-local rows) visible

        uint32_t pf[8][4];
        #pragma unroll
        for (int k8 = 0; k8 < 8; k8++){
            pf[k8][0] = __float_as_uint(QP[(q0+g  )*APAD + k8*8 + tg    ]);
            pf[k8][1] = __float_as_uint(QP[(q0+g+8)*APAD + k8*8 + tg    ]);
            pf[k8][2] = __float_as_uint(QP[(q0+g  )*APAD + k8*8 + tg + 4]);
            pf[k8][3] = __float_as_uint(QP[(q0+g+8)*APAD + k8*8 + tg + 4]);
        }
        #pragma unroll
        for (int n8 = 0; n8 < 8; n8++){
            #pragma unroll
            for (int k8 = 0; k8 < 8; k8++){
                uint32_t bf[2];
                bf[0] = __float_as_uint(Vs[(k8*8+tg  )*APAD + n8*8 + g]);
                bf[1] = __float_as_uint(Vs[(k8*8+tg+4)*APAD + n8*8 + g]);
                mma_tf32(o[n8], pf[k8], bf);
            }
        }
    }
    float inv0 = 1.f/l0, inv1 = 1.f/l1;
    int tok0 = b*S_LEN + qt*64 + q0 + g;
    int tok1 = tok0 + 8;
    #pragma unroll
    for (int n8 = 0; n8 < 8; n8++){
        int c = h*HD + n8*8 + 2*tg;
        *(float2*)&g_attn[(size_t)tok0*DIMV + c] = make_float2(o[n8][0]*inv0, o[n8][1]*inv0);
        *(float2*)&g_attn[(size_t)tok1*DIMV + c] = make_float2(o[n8][2]*inv1, o[n8][3]*inv1);
    }
}

// ---------------- TF32 GEMM, cp.async 3-stage pipeline ----------------
#define ASZ (128*36)
#define BSZ (32*136)
#define STG (ASZ+BSZ)

template<int EPI>
__global__ void __launch_bounds__(256,2) tgemm_kernel(
    const float* __restrict__ A, const float* __restrict__ B,
    const float* __restrict__ bias, const float* __restrict__ R,
    float* __restrict__ C, int M, int N, int K,
    long long sA, long long sB, long long sBias, long long sC)
{
    extern __shared__ float smem[];
    A    += (long long)blockIdx.z * sA;
    B    += (long long)blockIdx.z * sB;
    bias += (long long)blockIdx.z * sBias;
    C    += (long long)blockIdx.z * sC;
    const int m0 = blockIdx.y*128, n0 = blockIdx.x*128;
    const int tid  = threadIdx.x;
    const int warp = tid >> 5, lane = tid & 31;
    const int wM = warp & 1;
    const int wN = warp >> 1;
    const int g  = lane >> 2;
    const int tg = lane & 3;

    float acc[4][4][4];
    #pragma unroll
    for (int mi = 0; mi < 4; mi++)
        #pragma unroll
        for (int ni = 0; ni < 4; ni++)
            #pragma unroll
            for (int q = 0; q < 4; q++) acc[mi][ni][q] = 0.f;

    const int aRow = tid >> 3, aCol = (tid & 7)*4;
    const int bRow = tid >> 5, bCol = (tid & 31)*4;
    const float* Ag = A + (size_t)(m0 + aRow)*K + aCol;
    const float* Bg = B + (size_t)bRow*N + n0 + bCol;
    const int nkt = K >> 5;

    auto issue = [&](int kt){
        float* As_ = smem + (kt % 3)*STG;
        float* Bs_ = As_ + ASZ;
        const float* ag = Ag + kt*32;
        const float* bg = Bg + (size_t)kt*32*N;
        #pragma unroll
        for (int i = 0; i < 4; i++)
            cp_async16(&As_[(aRow + 32*i)*36 + aCol], ag + (size_t)(32*i)*K);
        #pragma unroll
        for (int i = 0; i < 4; i++)
            cp_async16(&Bs_[(bRow + 8*i)*136 + bCol], bg + (size_t)(8*i)*N);
        cp_commit();
    };

    issue(0); issue(1);

    for (int kt = 0; kt < nkt; kt++){
        cp_wait<1>();
        __syncthreads();
        if (kt + 2 < nkt) issue(kt + 2);
        const float* As_ = smem + (kt % 3)*STG;
        const float* Bs_ = As_ + ASZ;
        #pragma unroll
        for (int k8 = 0; k8 < 32; k8 += 8){
            uint32_t af[4][4], bf[4][2];
            #pragma unroll
            for (int mi = 0; mi < 4; mi++){
                int r = wM*64 + mi*16 + g;
                af[mi][0] = __float_as_uint(As_[(r    )*36 + k8 + tg    ]);
                af[mi][1] = __float_as_uint(As_[(r + 8)*36 + k8 + tg    ]);
                af[mi][2] = __float_as_uint(As_[(r    )*36 + k8 + tg + 4]);
                af[mi][3] = __float_as_uint(As_[(r + 8)*36 + k8 + tg + 4]);
            }
            #pragma unroll
            for (int ni = 0; ni < 4; ni++){
                int c = wN*32 + ni*8 + g;
                bf[ni][0] = __float_as_uint(Bs_[(k8 + tg    )*136 + c]);
                bf[ni][1] = __float_as_uint(Bs_[(k8 + tg + 4)*136 + c]);
            }
            #pragma unroll
            for (int mi = 0; mi < 4; mi++)
                #pragma unroll
                for (int ni = 0; ni < 4; ni++)
                    mma_tf32(acc[mi][ni], af[mi], bf[ni]);
        }
    }

    #pragma unroll
    for (int mi = 0; mi < 4; mi++){
        int r0 = m0 + wM*64 + mi*16 + g;
        #pragma unroll
        for (int ni = 0; ni < 4; ni++){
            int c0 = n0 + wN*32 + ni*8 + tg*2;
            float bv0 = bias[c0], bv1 = bias[c0+1];
            float v00 = acc[mi][ni][0] + bv0;
            float v01 = acc[mi][ni][1] + bv1;
            float v10 = acc[mi][ni][2] + bv0;
            float v11 = acc[mi][ni][3] + bv1;
            if (EPI == 1){
                v00 = gelu_f(v00); v01 = gelu_f(v01);
                v10 = gelu_f(v10); v11 = gelu_f(v11);
            }
            if (EPI == 2){
                v00 += R[(size_t)r0*N + c0];     v01 += R[(size_t)r0*N + c0 + 1];
                v10 += R[(size_t)(r0+8)*N + c0]; v11 += R[(size_t)(r0+8)*N + c0 + 1];
            }
            *(float2*)&C[(size_t)r0*N + c0]     = make_float2(v00, v01);
            *(float2*)&C[(size_t)(r0+8)*N + c0] = make_float2(v10, v11);
        }
    }
}

// ---------------- MoE routing ----------------
__global__ void gate_kernel(const float* __restrict__ gate_w){
    int t = blockIdx.x;
    int warp = threadIdx.x >> 5, lane = threadIdx.x & 31;
    const float* hr = g_h2 + (size_t)t*DIMV;
    float part = 0.f;
    for (int d = lane; d < DIMV; d += 32) part += hr[d]*gate_w[d*EXPERTS + warp];
    for (int o = 16; o; o >>= 1) part += __shfl_xor_sync(0xffffffffu, part, o);
    __shared__ float lg[EXPERTS];
    if (lane == 0) lg[warp] = part;
    __syncthreads();
    if (threadIdx.x == 0){
        float mx = -1e30f;
        for (int e = 0; e < EXPERTS; e++) mx = fmaxf(mx, lg[e]);
        float ex[EXPERTS], sum = 0.f;
        for (int e = 0; e < EXPERTS; e++){ ex[e] = expf(lg[e]-mx); sum += ex[e]; }
        float inv = 1.f/sum;
        float p[EXPERTS];
        for (int e = 0; e < EXPERTS; e++){ p[e] = ex[e]*inv; g_probs[t*EXPERTS + e] = p[e]; }
        int i1 = 0; float v1 = p[0];
        for (int e = 1; e < EXPERTS; e++) if (p[e] > v1){ v1 = p[e]; i1 = e; }
        int i2 = -1; float v2 = -1.f;
        for (int e = 0; e < EXPERTS; e++) if (e != i1 && p[e] > v2){ v2 = p[e]; i2 = e; }
        float ws = v1 + v2;
        g_eid[t]          = i1;  g_eid[T_TOK + t]  = i2;
        g_wass[t]         = v1/ws; g_wass[T_TOK + t] = v2/ws;
    }
}

// parallel rank-within-expert, preserving j = k*T + t order (matches topi.T.reshape(-1))
__global__ void __launch_bounds__(1024) pos_kernel(){
    int tid = threadIdx.x;             // 1024 threads, 8 assignments each
    int lane = tid & 31, warp = tid >> 5;
    __shared__ int wtot[EXPERTS][32];
    __shared__ int woff[EXPERTS][32];
    int e0[8];
    #pragma unroll
    for (int i = 0; i < 8; i++) e0[i] = g_eid[tid*8 + i];
    int cnt[EXPERTS];
    #pragma unroll
    for (int e = 0; e < EXPERTS; e++){
        int c = 0;
        #pragma unroll
        for (int i = 0; i < 8; i++) c += (e0[i] == e);
        cnt[e] = c;
    }
    int excl[EXPERTS];
    #pragma unroll
    for (int e = 0; e < EXPERTS; e++){
        int v = cnt[e];
        #pragma unroll
        for (int o = 1; o < 32; o <<= 1){
            int n = __shfl_up_sync(0xffffffffu, v, o);
            if (lane >= o) v += n;
        }
        excl[e] = v - cnt[e];
        if (lane == 31) wtot[e][warp] = v;
    }
    __syncthreads();
    if (warp < EXPERTS){
        int v = wtot[warp][lane];
        int orig = v;
        #pragma unroll
        for (int o = 1; o < 32; o <<= 1){
            int n = __shfl_up_sync(0xffffffffu, v, o);
            if (lane >= o) v += n;
        }
        woff[warp][lane] = v - orig;
        if (lane == 31) g_cnt[warp] = v;
    }
    __syncthreads();
    int run[EXPERTS];
    #pragma unroll
    for (int e = 0; e < EXPERTS; e++) run[e] = woff[e][warp] + excl[e];
    #pragma unroll
    for (int i = 0; i < 8; i++){
        int e = e0[i];
        int p = 0;
        #pragma unroll
        for (int q = 0; q < EXPERTS; q++) if (e == q){ p = run[q]; run[q]++; }
        g_pos[tid*8 + i]  = p;
        g_keep[tid*8 + i] = (p < CAP) ? 1 : 0;
    }
}

__global__ void scatter_kernel(){
    int j = blockIdx.x;
    if (!g_keep[j]) return;
    int tok = (j >= T_TOK) ? (j - T_TOK) : j;
    int e = g_eid[j], p = g_pos[j];
    const float* src = g_h2 + (size_t)tok*DIMV;
    float* dst = g_buf + ((size_t)e*CAP + p)*DIMV;
    for (int d = threadIdx.x; d < DIMV; d += 256) dst[d] = src[d];
}

__global__ void final_kernel(float* __restrict__ out){
    int t = blockIdx.x;
    int j0 = t, j1 = T_TOK + t;
    float w0 = g_keep[j0] ? g_wass[j0] : 0.f;
    float w1 = g_keep[j1] ? g_wass[j1] : 0.f;
    int p0 = min(g_pos[j0], CAP-1), p1 = min(g_pos[j1], CAP-1);
    size_t i0 = ((size_t)g_eid[j0]*CAP + p0)*DIMV;
    size_t i1 = ((size_t)g_eid[j1]*CAP + p1)*DIMV;
    const float* x2r = g_x2 + (size_t)t*DIMV;
    float* orow = out + (size_t)t*DIMV;
    for (int d = threadIdx.x; d < DIMV; d += 256)
        orow[d] = x2r[d] + w0*g_moe[i0 + d] + w1*g_moe[i1 + d];
}

__global__ void aux_kernel(float* __restrict__ out, int out_size){
    __shared__ float red[EXPERTS][257];
    float acc[EXPERTS];
    #pragma unroll
    for (int e = 0; e < EXPERTS; e++) acc[e] = 0.f;
    for (int t = threadIdx.x; t < T_TOK; t += 256){
        #pragma unroll
        for (int e = 0; e < EXPERTS; e++) acc[e] += g_probs[t*EXPERTS + e];
    }
    #pragma unroll
    for (int e = 0; e < EXPERTS; e++) red[e][threadIdx.x] = acc[e];
    __syncthreads();
    if (threadIdx.x == 0){
        float aux = 0.f;
        for (int e = 0; e < EXPERTS; e++){
            float s = 0.f;
            for (int i = 0; i < 256; i++) s += red[e][i];
            float me = s / (float)T_TOK;
            float ce = (float)g_cnt[e] / (float)(T_TOK*2);
            aux += me*ce;
        }
        if (out_size > T_TOK*DIMV) out[(size_t)T_TOK*DIMV] = (float)EXPERTS * aux;
    }
}

// ---------------- launch ----------------
#define GEMM_SMEM (3*STG*4)
#define ATTN_SMEM (3*64*APAD*4)

extern "C" void kernel_launch(void* const* d_in, const int* in_sizes, int n_in,
                              void* d_out, int out_size){
    const float* x      = (const float*)d_in[0];
    const float* cosp   = (const float*)d_in[1];
    const float* sinp   = (const float*)d_in[2];
    const float* ln1g   = (const float*)d_in[3];
    const float* ln1b   = (const float*)d_in[4];
    const float* ln2g   = (const float*)d_in[5];
    const float* ln2b   = (const float*)d_in[6];
    const float* wqkv   = (const float*)d_in[7];
    const float* bqkv   = (const float*)d_in[8];
    const float* wo     = (const float*)d_in[9];
    const float* bo     = (const float*)d_in[10];
    const float* gate_w = (const float*)d_in[11];
    const float* w1     = (const float*)d_in[12];
    const float* b1     = (const float*)d_in[13];
    const float* w2     = (const float*)d_in[14];
    const float* b2     = (const float*)d_in[15];
    float* out = (float*)d_out;

    float *p_h, *p_qkv, *p_attn, *p_x2, *p_h2, *p_buf, *p_mid, *p_moe;
    cudaGetSymbolAddress((void**)&p_h,    g_h);
    cudaGetSymbolAddress((void**)&p_qkv,  g_qkv);
    cudaGetSymbolAddress((void**)&p_attn, g_attn);
    cudaGetSymbolAddress((void**)&p_x2,   g_x2);
    cudaGetSymbolAddress((void**)&p_h2,   g_h2);
    cudaGetSymbolAddress((void**)&p_buf,  g_buf);
    cudaGetSymbolAddress((void**)&p_mid,  g_mid);
    cudaGetSymbolAddress((void**)&p_moe,  g_moe);

    cudaFuncSetAttribute(tgemm_kernel<0>, cudaFuncAttributeMaxDynamicSharedMemorySize, GEMM_SMEM);
    cudaFuncSetAttribute(tgemm_kernel<1>, cudaFuncAttributeMaxDynamicSharedMemorySize, GEMM_SMEM);
    cudaFuncSetAttribute(tgemm_kernel<2>, cudaFuncAttributeMaxDynamicSharedMemorySize, GEMM_SMEM);
    cudaFuncSetAttribute(attn_tc_kernel,  cudaFuncAttributeMaxDynamicSharedMemorySize, ATTN_SMEM);

    zero_kernel<<<512, 256>>>();
    ln_kernel<<<T_TOK, 256>>>(x, ln1g, ln1b, p_h);

    // qkv = h @ wqkv + bqkv
    tgemm_kernel<0><<<dim3(3072/128, T_TOK/128, 1), 256, GEMM_SMEM>>>(
        p_h, wqkv, bqkv, nullptr, p_qkv, T_TOK, 3072, DIMV, 0,0,0,0);

    rope_split_kernel<<<T_TOK, 256>>>(cosp, sinp);
    attn_tc_kernel<<<dim3(S_LEN/64, 2*HEADS), 128, ATTN_SMEM>>>();

    // x2 = attn @ wo + bo + x
    tgemm_kernel<2><<<dim3(DIMV/128, T_TOK/128, 1), 256, GEMM_SMEM>>>(
        p_attn, wo, bo, x, p_x2, T_TOK, DIMV, DIMV, 0,0,0,0);

    ln_kernel<<<T_TOK, 256>>>(p_x2, ln2g, ln2b, p_h2);
    gate_kernel<<<T_TOK, 256>>>(gate_w);
    pos_kernel<<<1, 1024>>>();
    scatter_kernel<<<NASSIGN, 256>>>();

    // mid = gelu(buf @ w1 + b1)
    tgemm_kernel<1><<<dim3(HIDDEN/128, CAP/128, EXPERTS), 256, GEMM_SMEM>>>(
        p_buf, w1, b1, nullptr, p_mid, CAP, HIDDEN, DIMV,
        (long long)CAP*DIMV, (long long)DIMV*HIDDEN, (long long)HIDDEN, (long long)CAP*HIDDEN);

    // moe = mid @ w2 + b2
    tgemm_kernel<0><<<dim3(DIMV/128, CAP/128, EXPERTS), 256, GEMM_SMEM>>>(
        p_mid, w2, b2, nullptr, p_moe, CAP, DIMV, HIDDEN,
        (long long)CAP*HIDDEN, (long long)HIDDEN*DIMV, (long long)DIMV, (long long)CAP*DIMV);

    final_kernel<<<T_TOK, 256>>>(out);
    aux_kernel<<<1, 256>>>(out, out_size);
}